// round 1
// baseline (speedup 1.0000x reference)
#include <cuda_runtime.h>
#include <math.h>
#include <stdint.h>

// ---------------- problem constants ----------------
#define CDIM   192
#define IMGHW  224
#define HW     (IMGHW*IMGHW)          // 50176
#define BATCH  4
#define HWC    ((size_t)CDIM*HW)      // 9,633,792
#define NWIN   3136                   // 4 * 28 * 28
#define NTOK   200704                 // NWIN * 64
#define NHEADS 6
#define OUT_MAIN ((size_t)BATCH*HWC)  // 38,535,168
#define RECON_DENOM 38535168.0

// ---------------- scratch (device globals; no runtime alloc) ----------------
__device__ float g_buf0[OUT_MAIN];      // f1 (conv1x1 out), later m (gate product)
__device__ float g_buf1[OUT_MAIN];      // f2 (dwconv out), later fused (proj out)
__device__ float g_p   [OUT_MAIN];      // LN'd window tokens [NWIN,64,192]
__device__ float g_qkv [(size_t)NTOK*576];
__device__ float g_h   [(size_t)NTOK*768];
__device__ float g_attn[OUT_MAIN];      // attention output [tok,192]
__device__ float g_loss[1];

// ---------------- generic fp32 GEMM: C[M,N] = A[M,K] @ B[K,N] + epilogue ----
// Tile 64x64, K-chunk 16, 256 threads, 4x4 micro-tile.
enum { EPI_BIASN = 0, EPI_BIASM = 1, EPI_GELU = 2, EPI_MUL = 3, EPI_LOSS = 4 };

template<int EPI>
__global__ void __launch_bounds__(256)
sgemm_kernel(const float* __restrict__ A, int lda,
             const float* __restrict__ B, int ldb, size_t bz,
             float* __restrict__ C, int ldc, size_t cz,
             const float* __restrict__ bias,
             int K,
             const float* __restrict__ extra,   // gate (MUL) or p (LOSS)
             float* __restrict__ lossAcc)
{
    __shared__ __align__(16) float As[16][68];
    __shared__ __align__(16) float Bs[16][68];
    __shared__ float red[256];

    const float* Bp = B + (size_t)blockIdx.z * bz;
    float* Cp = C + (size_t)blockIdx.z * cz;

    const int bm = blockIdx.y * 64;
    const int bn = blockIdx.x * 64;
    const int tid = threadIdx.x;
    const int tx = tid & 15, ty = tid >> 4;

    float acc[4][4] = {};

    for (int k0 = 0; k0 < K; k0 += 16) {
        #pragma unroll
        for (int i = 0; i < 4; i++) {
            int idx = tid + i * 256;       // 0..1023
            int m = idx >> 4, kk = idx & 15;
            As[kk][m] = A[(size_t)(bm + m) * lda + (k0 + kk)];
        }
        #pragma unroll
        for (int i = 0; i < 4; i++) {
            int idx = tid + i * 256;
            int kk = idx >> 6, n = idx & 63;
            Bs[kk][n] = Bp[(size_t)(k0 + kk) * ldb + (bn + n)];
        }
        __syncthreads();
        #pragma unroll
        for (int kk = 0; kk < 16; kk++) {
            float4 av = *(const float4*)&As[kk][ty * 4];
            float4 bv = *(const float4*)&Bs[kk][tx * 4];
            float a[4] = {av.x, av.y, av.z, av.w};
            float b[4] = {bv.x, bv.y, bv.z, bv.w};
            #pragma unroll
            for (int i = 0; i < 4; i++)
                #pragma unroll
                for (int j = 0; j < 4; j++)
                    acc[i][j] = fmaf(a[i], b[j], acc[i][j]);
        }
        __syncthreads();
    }

    float lsum = 0.f;
    #pragma unroll
    for (int i = 0; i < 4; i++) {
        int m = bm + ty * 4 + i;
        #pragma unroll
        for (int j = 0; j < 4; j++) {
            int n = bn + tx * 4 + j;
            float v = acc[i][j];
            if (EPI == EPI_BIASM) v += bias[m];
            else                  v += bias[n];
            if (EPI == EPI_GELU)
                v = 0.5f * v * (1.0f + erff(v * 0.70710678118654752f));
            size_t ci = (size_t)m * ldc + n;
            if (EPI == EPI_MUL)  v *= extra[ci];
            if (EPI == EPI_LOSS) {
                lsum += fabsf(v - extra[ci]);
            } else {
                Cp[ci] = v;
            }
        }
    }

    if (EPI == EPI_LOSS) {
        red[tid] = lsum;
        __syncthreads();
        #pragma unroll
        for (int s = 128; s > 0; s >>= 1) {
            if (tid < s) red[tid] += red[tid + s];
            __syncthreads();
        }
        if (tid == 0) atomicAdd(lossAcc, red[0]);
    }
}

// ---------------- depthwise 3x3, SAME, NCHW ----------------
__global__ void __launch_bounds__(256)
dwconv_kernel(const float* __restrict__ in, const float* __restrict__ w,
              const float* __restrict__ bias, float* __restrict__ out)
{
    size_t idx = (size_t)blockIdx.x * 256 + threadIdx.x;   // exact grid
    int xq = (int)(idx % IMGHW);
    int yq = (int)((idx / IMGHW) % IMGHW);
    int c  = (int)((idx / HW) % CDIM);
    const float* wp = &w[c * 9];
    const float* plane = in + (idx - xq - (size_t)yq * IMGHW);
    float acc = bias[c];
    #pragma unroll
    for (int ky = 0; ky < 3; ky++) {
        int yy = yq + ky - 1;
        if (yy < 0 || yy >= IMGHW) continue;
        #pragma unroll
        for (int kx = 0; kx < 3; kx++) {
            int xx = xq + kx - 1;
            if (xx < 0 || xx >= IMGHW) continue;
            acc = fmaf(plane[(size_t)yy * IMGHW + xx], wp[ky * 3 + kx], acc);
        }
    }
    out[idx] = acc;
}

// ---------------- LayerNorm(channel) + window partition ----------------
// One block per window. Dynamic smem tile[64][193] (49408 B).
__global__ void __launch_bounds__(256)
ln_partition_kernel(const float* __restrict__ f2,
                    const float* __restrict__ lng, const float* __restrict__ lnb,
                    float* __restrict__ p)
{
    extern __shared__ float tile[];       // [64][193]
    __shared__ float mu[64], rs[64];

    int win = blockIdx.x;
    int b  = win / 784;
    int wr = win % 784;
    int wy = wr / 28, wx = wr % 28;
    size_t base = (size_t)b * HWC + (size_t)(wy * 8) * IMGHW + wx * 8;

    for (int idx = threadIdx.x; idx < 64 * 192; idx += 256) {
        int c = idx >> 6, t = idx & 63;
        int iy = t >> 3, ix = t & 7;
        tile[t * 193 + c] = f2[base + (size_t)c * HW + iy * IMGHW + ix];
    }
    __syncthreads();

    if (threadIdx.x < 64) {
        int t = threadIdx.x;
        float s = 0.f, s2 = 0.f;
        for (int c = 0; c < 192; c++) {
            float v = tile[t * 193 + c];
            s += v; s2 = fmaf(v, v, s2);
        }
        float m = s * (1.0f / 192.0f);
        float var = s2 * (1.0f / 192.0f) - m * m;
        mu[t] = m;
        rs[t] = rsqrtf(var + 1e-6f);
    }
    __syncthreads();

    size_t pb = (size_t)win * (64 * 192);
    for (int idx = threadIdx.x; idx < 64 * 192; idx += 256) {
        int t = idx / 192, c = idx % 192;
        float v = (tile[t * 193 + c] - mu[t]) * rs[t];
        p[pb + idx] = fmaf(v, lng[c], lnb[c]);
    }
}

// ---------------- windowed multi-head attention ----------------
// One block per (window, head). 64 threads; thread r owns query row r.
__global__ void __launch_bounds__(64)
attention_kernel(const float* __restrict__ qkv, float* __restrict__ outat)
{
    __shared__ float ks[64][33];
    __shared__ float vs[64][33];
    __shared__ float ps[64][65];

    int bid = blockIdx.x;
    int win = bid / NHEADS, h = bid % NHEADS;
    size_t qbase = (size_t)win * 64 * 576;
    int hc = h * 32;

    for (int idx = threadIdx.x; idx < 64 * 32; idx += 64) {
        int t = idx >> 5, c = idx & 31;
        ks[t][c] = qkv[qbase + (size_t)t * 576 + 192 + hc + c];
        vs[t][c] = qkv[qbase + (size_t)t * 576 + 384 + hc + c];
    }
    __syncthreads();

    int r = threadIdx.x;
    float q[32];
    const float* qp = &qkv[qbase + (size_t)r * 576 + hc];
    #pragma unroll
    for (int c = 0; c < 32; c++) q[c] = qp[c];

    float mx = -1e30f;
    for (int t = 0; t < 64; t++) {
        float d = 0.f;
        #pragma unroll
        for (int c = 0; c < 32; c++) d = fmaf(q[c], ks[t][c], d);
        d *= 0.17677669529663687f;   // 32^-0.5
        ps[r][t] = d;
        mx = fmaxf(mx, d);
    }
    float sum = 0.f;
    for (int t = 0; t < 64; t++) {
        float e = expf(ps[r][t] - mx);
        ps[r][t] = e;
        sum += e;
    }
    float inv = 1.0f / sum;

    float* op = &outat[((size_t)win * 64 + r) * 192 + hc];
    for (int c = 0; c < 32; c++) {
        float a = 0.f;
        for (int t = 0; t < 64; t++) a = fmaf(ps[r][t], vs[t][c], a);
        op[c] = a * inv;
    }
}

// ---------------- window reverse + residual ----------------
__global__ void __launch_bounds__(256)
reverse_residual_kernel(const float* __restrict__ fused,
                        const float* __restrict__ xin,
                        float* __restrict__ out)
{
    extern __shared__ float tile[];       // [64][193]
    int win = blockIdx.x;
    size_t fb = (size_t)win * (64 * 192);

    for (int idx = threadIdx.x; idx < 64 * 192; idx += 256) {
        int t = idx / 192, c = idx % 192;
        tile[t * 193 + c] = fused[fb + idx];
    }
    __syncthreads();

    int b  = win / 784;
    int wr = win % 784;
    int wy = wr / 28, wx = wr % 28;
    size_t base = (size_t)b * HWC + (size_t)(wy * 8) * IMGHW + wx * 8;

    for (int idx = threadIdx.x; idx < 64 * 192; idx += 256) {
        int c = idx >> 6, t = idx & 63;
        int iy = t >> 3, ix = t & 7;
        size_t o = base + (size_t)c * HW + iy * IMGHW + ix;
        out[o] = tile[t * 193 + c] + xin[o];
    }
}

// ---------------- tiny helpers ----------------
__global__ void zero_loss_kernel(float* l) { *l = 0.f; }
__global__ void finalize_loss_kernel(const float* l, float* out, size_t pos)
{
    out[pos] = l[0] * (float)(0.1 / RECON_DENOM);
}

// ---------------- launch ----------------
extern "C" void kernel_launch(void* const* d_in, const int* in_sizes, int n_in,
                              void* d_out, int out_size)
{
    const float* x      = (const float*)d_in[0];
    const float* w_pre1 = (const float*)d_in[1];
    const float* b_pre1 = (const float*)d_in[2];
    const float* w_dw   = (const float*)d_in[3];
    const float* b_dw   = (const float*)d_in[4];
    const float* ln_g   = (const float*)d_in[5];
    const float* ln_b   = (const float*)d_in[6];
    const float* w_qkv  = (const float*)d_in[7];
    const float* b_qkv  = (const float*)d_in[8];
    const float* w_proj = (const float*)d_in[9];
    const float* b_proj = (const float*)d_in[10];
    const float* w_g1   = (const float*)d_in[11];
    const float* b_g1   = (const float*)d_in[12];
    const float* w_g2   = (const float*)d_in[13];
    const float* b_g2   = (const float*)d_in[14];
    const float* w_rec  = (const float*)d_in[15];
    const float* b_rec  = (const float*)d_in[16];
    float* out = (float*)d_out;

    float *f1, *f2, *p, *qkv, *h, *attn, *loss;
    cudaGetSymbolAddress((void**)&f1,   g_buf0);
    cudaGetSymbolAddress((void**)&f2,   g_buf1);
    cudaGetSymbolAddress((void**)&p,    g_p);
    cudaGetSymbolAddress((void**)&qkv,  g_qkv);
    cudaGetSymbolAddress((void**)&h,    g_h);
    cudaGetSymbolAddress((void**)&attn, g_attn);
    cudaGetSymbolAddress((void**)&loss, g_loss);
    float* m     = f1;   // reuse: f1 dead after dwconv
    float* fused = f2;   // reuse: f2 dead after LN

    const int TILE_SMEM = 64 * 193 * 4;  // 49408 B > 48KB static limit
    cudaFuncSetAttribute(ln_partition_kernel,
                         cudaFuncAttributeMaxDynamicSharedMemorySize, TILE_SMEM);
    cudaFuncSetAttribute(reverse_residual_kernel,
                         cudaFuncAttributeMaxDynamicSharedMemorySize, TILE_SMEM);

    zero_loss_kernel<<<1, 1>>>(loss);

    // 1) 1x1 conv: f1[b,o,s] = sum_c w_pre1[o,c] * x[b,c,s] + b_pre1[o]
    sgemm_kernel<EPI_BIASM><<<dim3(HW / 64, CDIM / 64, BATCH), 256>>>(
        w_pre1, CDIM, x, HW, HWC, f1, HW, HWC, b_pre1, CDIM, nullptr, nullptr);

    // 2) depthwise 3x3
    dwconv_kernel<<<(unsigned)(OUT_MAIN / 256), 256>>>(f1, w_dw, b_dw, f2);

    // 3) LN + window partition -> p [NWIN,64,192]
    ln_partition_kernel<<<NWIN, 256, TILE_SMEM>>>(f2, ln_g, ln_b, p);

    // 4) qkv = p @ w_qkv + b
    sgemm_kernel<EPI_BIASN><<<dim3(576 / 64, NTOK / 64, 1), 256>>>(
        p, CDIM, w_qkv, 576, 0, qkv, 576, 0, b_qkv, CDIM, nullptr, nullptr);

    // 5) windowed attention -> attn [tok,192]
    attention_kernel<<<NWIN * NHEADS, 64>>>(qkv, attn);

    // 6) h = gelu(v @ w_g1 + b_g1)   (v = qkv cols 384..575)
    sgemm_kernel<EPI_GELU><<<dim3(768 / 64, NTOK / 64, 1), 256>>>(
        qkv + 384, 576, w_g1, 768, 0, h, 768, 0, b_g1, CDIM, nullptr, nullptr);

    // 7) m = (h @ w_g2 + b_g2) * attn
    sgemm_kernel<EPI_MUL><<<dim3(CDIM / 64, NTOK / 64, 1), 256>>>(
        h, 768, w_g2, CDIM, 0, m, CDIM, 0, b_g2, 768, attn, nullptr);

    // 8) fused = m @ w_proj + b_proj
    sgemm_kernel<EPI_BIASN><<<dim3(CDIM / 64, NTOK / 64, 1), 256>>>(
        m, CDIM, w_proj, CDIM, 0, fused, CDIM, 0, b_proj, CDIM, nullptr, nullptr);

    // 9) recon GEMM fused with L1 loss accumulation (recon never stored)
    sgemm_kernel<EPI_LOSS><<<dim3(CDIM / 64, NTOK / 64, 1), 256>>>(
        fused, CDIM, w_rec, CDIM, 0, fused /*unused*/, CDIM, 0, b_rec, CDIM, p, loss);

    // 10) window reverse + residual -> main output
    reverse_residual_kernel<<<NWIN, 256, TILE_SMEM>>>(fused, x, out);

    // 11) loss scalar at tail of d_out
    if ((size_t)out_size > OUT_MAIN)
        finalize_loss_kernel<<<1, 1>>>(loss, out, (size_t)out_size - 1);
}

// round 3
// speedup vs baseline: 2.4639x; 2.4639x over previous
#include <cuda_runtime.h>
#include <cuda_bf16.h>
#include <math.h>
#include <stdint.h>

// ---------------- problem constants ----------------
#define CDIM   192
#define IMGHW  224
#define HW     (IMGHW*IMGHW)          // 50176
#define BATCH  4
#define HWC    ((size_t)CDIM*HW)
#define NWIN   3136
#define NTOK   200704                 // NWIN * 64 == BATCH*HW
#define NHEADS 6
#define OUT_MAIN ((size_t)BATCH*HWC)  // 38,535,168
#define RECON_DENOM 38535168.0

// ---------------- scratch (device globals) ----------------
__device__ __align__(16) float g_attn[OUT_MAIN/0x1p0 == 0 ? 1 : (size_t)NTOK*192];
__device__ __align__(16) float g_f2  [(size_t)NTOK*192];   // NHWC dwconv out; later fused fp32
__device__ __align__(16) float g_p   [(size_t)NTOK*192];   // fp32 p (for loss)
__device__ __align__(16) __nv_bfloat16 g_pb   [(size_t)NTOK*192];  // xT first, then pb
__device__ __align__(16) __nv_bfloat16 g_qkvb [(size_t)NTOK*576];  // f1b first, then qkv
__device__ __align__(16) __nv_bfloat16 g_hb   [(size_t)NTOK*768];
__device__ __align__(16) __nv_bfloat16 g_mb   [(size_t)NTOK*192];
__device__ __align__(16) __nv_bfloat16 g_fusedb[(size_t)NTOK*192];
__device__ __align__(16) __nv_bfloat16 g_wt_pre [192*192];
__device__ __align__(16) __nv_bfloat16 g_wt_qkv [576*192];
__device__ __align__(16) __nv_bfloat16 g_wt_g1  [768*192];
__device__ __align__(16) __nv_bfloat16 g_wt_g2  [192*768];
__device__ __align__(16) __nv_bfloat16 g_wt_proj[192*192];
__device__ __align__(16) __nv_bfloat16 g_wt_rec [192*192];
__device__ float g_loss[1];

// ---------------- HMMA m16n8k16 bf16 helper ----------------
__device__ __forceinline__ void mma_bf16(float c[4],
    uint32_t a0, uint32_t a1, uint32_t a2, uint32_t a3,
    uint32_t b0, uint32_t b1)
{
    asm volatile(
        "mma.sync.aligned.m16n8k16.row.col.f32.bf16.bf16.f32 "
        "{%0,%1,%2,%3}, {%4,%5,%6,%7}, {%8,%9}, {%0,%1,%2,%3};"
        : "+f"(c[0]), "+f"(c[1]), "+f"(c[2]), "+f"(c[3])
        : "r"(a0), "r"(a1), "r"(a2), "r"(a3), "r"(b0), "r"(b1));
}

// ---------------- HMMA GEMM ----------------
// C[M, Ntot] = A[M,K]bf16 @ BT[Ntot,K]bf16^T + fused epilogue.
// CTA tile 128 x 64, K-chunk 32, double buffered, 256 threads (8 warps 4x2).
enum { E_BIASN = 0, E_GELU = 1, E_MUL = 2, E_PROJ = 3, E_LOSS = 4 };

template<int EPI>
__global__ void __launch_bounds__(256)
hmma_gemm(const __nv_bfloat16* __restrict__ A, int lda,
          const __nv_bfloat16* __restrict__ BT, int K,
          const float* __restrict__ bias,
          float* __restrict__ Cf,
          __nv_bfloat16* __restrict__ Cb, int ldc,
          const float* __restrict__ extra,
          float* __restrict__ lossAcc)
{
    __shared__ __align__(16) __nv_bfloat16 sA[2][128][40];
    __shared__ __align__(16) __nv_bfloat16 sB[2][64][40];
    __shared__ float red[256];

    const int tid = threadIdx.x;
    const int lane = tid & 31, wid = tid >> 5;
    const int wm = wid & 3, wn = wid >> 2;

    const __nv_bfloat16* Ab = A + (size_t)(blockIdx.y * 128) * lda;
    const __nv_bfloat16* Bb = BT + (size_t)(blockIdx.x * 64) * K;

    float acc[2][4][4] = {};
    const int nk = K >> 5;

    // chunk loader: 128x32 A (512 uint4), 64x32 B (256 uint4)
    #define LOAD_CHUNK(buf, k0) do {                                          \
        _Pragma("unroll")                                                     \
        for (int it = 0; it < 2; it++) {                                      \
            int id = tid + it * 256;                                          \
            int r = id >> 2, q = id & 3;                                      \
            *(uint4*)&sA[buf][r][q * 8] =                                     \
                *(const uint4*)(Ab + (size_t)r * lda + (k0) + q * 8);         \
        }                                                                     \
        {                                                                     \
            int r = tid >> 2, q = tid & 3;                                    \
            *(uint4*)&sB[buf][r][q * 8] =                                     \
                *(const uint4*)(Bb + (size_t)r * K + (k0) + q * 8);           \
        }                                                                     \
    } while (0)

    LOAD_CHUNK(0, 0);
    __syncthreads();

    for (int kc = 0; kc < nk; kc++) {
        int b = kc & 1;
        if (kc + 1 < nk) { LOAD_CHUNK(b ^ 1, (kc + 1) * 32); }

        #pragma unroll
        for (int ks = 0; ks < 2; ks++) {
            const int kof = ks * 16 + (lane & 3) * 2;
            uint32_t af[2][4];
            #pragma unroll
            for (int mi = 0; mi < 2; mi++) {
                int r = wm * 32 + mi * 16 + (lane >> 2);
                af[mi][0] = *(const uint32_t*)&sA[b][r][kof];
                af[mi][1] = *(const uint32_t*)&sA[b][r + 8][kof];
                af[mi][2] = *(const uint32_t*)&sA[b][r][kof + 8];
                af[mi][3] = *(const uint32_t*)&sA[b][r + 8][kof + 8];
            }
            uint32_t bfr[4][2];
            #pragma unroll
            for (int ni = 0; ni < 4; ni++) {
                int n = wn * 32 + ni * 8 + (lane >> 2);
                bfr[ni][0] = *(const uint32_t*)&sB[b][n][kof];
                bfr[ni][1] = *(const uint32_t*)&sB[b][n][kof + 8];
            }
            #pragma unroll
            for (int mi = 0; mi < 2; mi++)
                #pragma unroll
                for (int ni = 0; ni < 4; ni++)
                    mma_bf16(acc[mi][ni], af[mi][0], af[mi][1], af[mi][2],
                             af[mi][3], bfr[ni][0], bfr[ni][1]);
        }
        __syncthreads();
    }
    #undef LOAD_CHUNK

    // ---------------- epilogue ----------------
    float lsum = 0.f;
    #pragma unroll
    for (int mi = 0; mi < 2; mi++) {
        #pragma unroll
        for (int ni = 0; ni < 4; ni++) {
            int r0 = blockIdx.y * 128 + wm * 32 + mi * 16 + (lane >> 2);
            int n0 = blockIdx.x * 64 + wn * 32 + ni * 8 + (lane & 3) * 2;
            float b0 = bias[n0], b1 = bias[n0 + 1];
            #pragma unroll
            for (int h = 0; h < 2; h++) {
                int r = r0 + h * 8;
                float v0 = acc[mi][ni][2 * h] + b0;
                float v1 = acc[mi][ni][2 * h + 1] + b1;
                if (EPI == E_GELU) {
                    v0 = 0.5f * v0 * (1.0f + erff(v0 * 0.70710678118654752f));
                    v1 = 0.5f * v1 * (1.0f + erff(v1 * 0.70710678118654752f));
                }
                size_t ci = (size_t)r * ldc + n0;
                if (EPI == E_MUL) { v0 *= extra[ci]; v1 *= extra[ci + 1]; }
                if (EPI == E_LOSS) {
                    lsum += fabsf(v0 - extra[ci]) + fabsf(v1 - extra[ci + 1]);
                } else {
                    __nv_bfloat162 h2 = __floats2bfloat162_rn(v0, v1);
                    *(uint32_t*)(Cb + ci) = *(uint32_t*)&h2;
                    if (EPI == E_PROJ)
                        *(float2*)(Cf + ci) = make_float2(v0, v1);
                }
            }
        }
    }

    if (EPI == E_LOSS) {
        red[tid] = lsum;
        __syncthreads();
        #pragma unroll
        for (int s = 128; s > 0; s >>= 1) {
            if (tid < s) red[tid] += red[tid + s];
            __syncthreads();
        }
        if (tid == 0) atomicAdd(lossAcc, red[0]);
    }
}

// ---------------- x transpose: NCHW fp32 -> NHWC bf16 ----------------
__global__ void __launch_bounds__(256)
transpose_x_kernel(const float* __restrict__ x, __nv_bfloat16* __restrict__ xt)
{
    __shared__ float tile[32][33];
    int s0 = blockIdx.x * 32, c0 = blockIdx.y * 32, b = blockIdx.z;
    int tx = threadIdx.x & 31, ty = threadIdx.x >> 5;   // 32 x 8
    const float* xp = x + (size_t)b * HWC;
    #pragma unroll
    for (int j = 0; j < 4; j++)
        tile[ty + 8 * j][tx] = xp[(size_t)(c0 + ty + 8 * j) * HW + s0 + tx];
    __syncthreads();
    __nv_bfloat16* op = xt + (size_t)b * HW * CDIM;
    #pragma unroll
    for (int j = 0; j < 4; j++)
        op[(size_t)(s0 + ty + 8 * j) * CDIM + c0 + tx] =
            __float2bfloat16(tile[tx][ty + 8 * j]);
}

// ---------------- depthwise 3x3, NHWC, bf16 in / fp32 out ----------------
__global__ void __launch_bounds__(192)
dwconv_nhwc_kernel(const __nv_bfloat16* __restrict__ in,
                   const float* __restrict__ w, const float* __restrict__ bias,
                   float* __restrict__ out)
{
    int c = threadIdx.x;
    int pix = blockIdx.x;
    int b = pix / HW, s = pix % HW;
    int y = s / IMGHW, xq = s % IMGHW;
    const __nv_bfloat16* ip = in + (size_t)b * HW * CDIM;
    float acc = bias[c];
    #pragma unroll
    for (int ky = 0; ky < 3; ky++) {
        int yy = y + ky - 1;
        if (yy < 0 || yy >= IMGHW) continue;
        #pragma unroll
        for (int kx = 0; kx < 3; kx++) {
            int xx = xq + kx - 1;
            if (xx < 0 || xx >= IMGHW) continue;
            acc = fmaf(__bfloat162float(ip[(size_t)(yy * IMGHW + xx) * CDIM + c]),
                       w[c * 9 + ky * 3 + kx], acc);
        }
    }
    out[(size_t)pix * CDIM + c] = acc;
}

// ---------------- LayerNorm + window partition (NHWC fp32 in) ------------
__global__ void __launch_bounds__(256)
ln_partition_kernel(const float* __restrict__ f2,
                    const float* __restrict__ lng, const float* __restrict__ lnb,
                    float* __restrict__ p, __nv_bfloat16* __restrict__ pb)
{
    extern __shared__ float tile[];    // [64][193]
    __shared__ float mu[64], rs[64];
    int win = blockIdx.x;
    int b  = win / 784;
    int wr = win % 784;
    int wy = wr / 28, wx = wr % 28;
    const float* fp = f2 + (size_t)b * HW * CDIM;

    for (int idx = threadIdx.x; idx < 64 * 192; idx += 256) {
        int t = idx / 192, c = idx % 192;
        int iy = t >> 3, ix = t & 7;
        tile[t * 193 + c] =
            fp[(size_t)((wy * 8 + iy) * IMGHW + wx * 8 + ix) * CDIM + c];
    }
    __syncthreads();
    if (threadIdx.x < 64) {
        int t = threadIdx.x;
        float s = 0.f, s2 = 0.f;
        for (int c = 0; c < 192; c++) {
            float v = tile[t * 193 + c];
            s += v; s2 = fmaf(v, v, s2);
        }
        float m = s * (1.0f / 192.0f);
        float var = s2 * (1.0f / 192.0f) - m * m;
        mu[t] = m;
        rs[t] = rsqrtf(var + 1e-6f);
    }
    __syncthreads();
    size_t pbase = (size_t)win * (64 * 192);
    for (int idx = threadIdx.x; idx < 64 * 192; idx += 256) {
        int t = idx / 192, c = idx % 192;
        float v = (tile[t * 193 + c] - mu[t]) * rs[t];
        v = fmaf(v, lng[c], lnb[c]);
        p[pbase + idx] = v;
        pb[pbase + idx] = __float2bfloat16(v);
    }
}

// ---------------- windowed multi-head attention (bf16 qkv in) ------------
__global__ void __launch_bounds__(64)
attention_kernel(const __nv_bfloat16* __restrict__ qkv, float* __restrict__ outat)
{
    __shared__ float ks[64][33];
    __shared__ float vs[64][33];
    __shared__ float ps[64][65];
    int bid = blockIdx.x;
    int win = bid / NHEADS, h = bid % NHEADS;
    size_t qbase = (size_t)win * 64 * 576;
    int hc = h * 32;

    for (int idx = threadIdx.x; idx < 64 * 32; idx += 64) {
        int t = idx >> 5, c = idx & 31;
        ks[t][c] = __bfloat162float(qkv[qbase + (size_t)t * 576 + 192 + hc + c]);
        vs[t][c] = __bfloat162float(qkv[qbase + (size_t)t * 576 + 384 + hc + c]);
    }
    __syncthreads();

    int r = threadIdx.x;
    float q[32];
    const __nv_bfloat16* qp = &qkv[qbase + (size_t)r * 576 + hc];
    #pragma unroll
    for (int c = 0; c < 32; c++) q[c] = __bfloat162float(qp[c]);

    float mx = -1e30f;
    for (int t = 0; t < 64; t++) {
        float d = 0.f;
        #pragma unroll
        for (int c = 0; c < 32; c++) d = fmaf(q[c], ks[t][c], d);
        d *= 0.17677669529663687f;
        ps[r][t] = d;
        mx = fmaxf(mx, d);
    }
    float sum = 0.f;
    for (int t = 0; t < 64; t++) {
        float e = expf(ps[r][t] - mx);
        ps[r][t] = e;
        sum += e;
    }
    float inv = 1.0f / sum;
    float* op = &outat[((size_t)win * 64 + r) * 192 + hc];
    for (int c = 0; c < 32; c++) {
        float a = 0.f;
        for (int t = 0; t < 64; t++) a = fmaf(ps[r][t], vs[t][c], a);
        op[c] = a * inv;
    }
}

// ---------------- window reverse + residual (to NCHW) ----------------
__global__ void __launch_bounds__(256)
reverse_residual_kernel(const float* __restrict__ fused,
                        const float* __restrict__ xin,
                        float* __restrict__ out)
{
    extern __shared__ float tile[];    // [64][193]
    int win = blockIdx.x;
    size_t fb = (size_t)win * (64 * 192);
    for (int idx = threadIdx.x; idx < 64 * 192; idx += 256) {
        int t = idx / 192, c = idx % 192;
        tile[t * 193 + c] = fused[fb + idx];
    }
    __syncthreads();
    int b  = win / 784;
    int wr = win % 784;
    int wy = wr / 28, wx = wr % 28;
    size_t base = (size_t)b * HWC + (size_t)(wy * 8) * IMGHW + wx * 8;
    for (int idx = threadIdx.x; idx < 64 * 192; idx += 256) {
        int c = idx >> 6, t = idx & 63;
        int iy = t >> 3, ix = t & 7;
        size_t o = base + (size_t)c * HW + iy * IMGHW + ix;
        out[o] = tile[t * 193 + c] + xin[o];
    }
}

// ---------------- weight prep ----------------
__global__ void transpose_w_kernel(const float* __restrict__ w,
                                   __nv_bfloat16* __restrict__ wt, int K, int N)
{
    int i = blockIdx.x * 256 + threadIdx.x;
    if (i < K * N) {
        int k = i / N, n = i % N;
        wt[n * K + k] = __float2bfloat16(w[i]);
    }
}
__global__ void convert_w_kernel(const float* __restrict__ w,
                                 __nv_bfloat16* __restrict__ wt, int n)
{
    int i = blockIdx.x * 256 + threadIdx.x;
    if (i < n) wt[i] = __float2bfloat16(w[i]);
}

// ---------------- tiny helpers ----------------
__global__ void zero_loss_kernel(float* l) { *l = 0.f; }
__global__ void finalize_loss_kernel(const float* l, float* out, size_t pos)
{
    out[pos] = l[0] * (float)(0.1 / RECON_DENOM);
}

// ---------------- launch ----------------
extern "C" void kernel_launch(void* const* d_in, const int* in_sizes, int n_in,
                              void* d_out, int out_size)
{
    const float* x      = (const float*)d_in[0];
    const float* w_pre1 = (const float*)d_in[1];
    const float* b_pre1 = (const float*)d_in[2];
    const float* w_dw   = (const float*)d_in[3];
    const float* b_dw   = (const float*)d_in[4];
    const float* ln_g   = (const float*)d_in[5];
    const float* ln_b   = (const float*)d_in[6];
    const float* w_qkv  = (const float*)d_in[7];
    const float* b_qkv  = (const float*)d_in[8];
    const float* w_proj = (const float*)d_in[9];
    const float* b_proj = (const float*)d_in[10];
    const float* w_g1   = (const float*)d_in[11];
    const float* b_g1   = (const float*)d_in[12];
    const float* w_g2   = (const float*)d_in[13];
    const float* b_g2   = (const float*)d_in[14];
    const float* w_rec  = (const float*)d_in[15];
    const float* b_rec  = (const float*)d_in[16];
    float* out = (float*)d_out;

    float *attn, *f2, *p, *loss;
    __nv_bfloat16 *pb, *qkvb, *hb, *mb, *fusedb;
    __nv_bfloat16 *wtpre, *wtq, *wtg1, *wtg2, *wtp, *wtr;
    cudaGetSymbolAddress((void**)&attn,  g_attn);
    cudaGetSymbolAddress((void**)&f2,    g_f2);
    cudaGetSymbolAddress((void**)&p,     g_p);
    cudaGetSymbolAddress((void**)&pb,    g_pb);
    cudaGetSymbolAddress((void**)&qkvb,  g_qkvb);
    cudaGetSymbolAddress((void**)&hb,    g_hb);
    cudaGetSymbolAddress((void**)&mb,    g_mb);
    cudaGetSymbolAddress((void**)&fusedb, g_fusedb);
    cudaGetSymbolAddress((void**)&wtpre, g_wt_pre);
    cudaGetSymbolAddress((void**)&wtq,   g_wt_qkv);
    cudaGetSymbolAddress((void**)&wtg1,  g_wt_g1);
    cudaGetSymbolAddress((void**)&wtg2,  g_wt_g2);
    cudaGetSymbolAddress((void**)&wtp,   g_wt_proj);
    cudaGetSymbolAddress((void**)&wtr,   g_wt_rec);
    cudaGetSymbolAddress((void**)&loss,  g_loss);

    __nv_bfloat16* xt  = pb;     // xT dead before pb is written (by LN)
    __nv_bfloat16* f1b = qkvb;   // f1b dead before qkv GEMM writes
    float* fused = f2;           // f2 dead after LN

    const int TILE_SMEM = 64 * 193 * 4;
    cudaFuncSetAttribute(ln_partition_kernel,
                         cudaFuncAttributeMaxDynamicSharedMemorySize, TILE_SMEM);
    cudaFuncSetAttribute(reverse_residual_kernel,
                         cudaFuncAttributeMaxDynamicSharedMemorySize, TILE_SMEM);

    zero_loss_kernel<<<1, 1>>>(loss);

    // weight prep (tiny)
    convert_w_kernel<<<(192*192 + 255) / 256, 256>>>(w_pre1, wtpre, 192*192);
    transpose_w_kernel<<<(192*576 + 255) / 256, 256>>>(w_qkv, wtq, 192, 576);
    transpose_w_kernel<<<(192*768 + 255) / 256, 256>>>(w_g1, wtg1, 192, 768);
    transpose_w_kernel<<<(768*192 + 255) / 256, 256>>>(w_g2, wtg2, 768, 192);
    transpose_w_kernel<<<(192*192 + 255) / 256, 256>>>(w_proj, wtp, 192, 192);
    transpose_w_kernel<<<(192*192 + 255) / 256, 256>>>(w_rec, wtr, 192, 192);

    // 0) x -> NHWC bf16
    transpose_x_kernel<<<dim3(HW / 32, CDIM / 32, BATCH), 256>>>(x, xt);

    // 1) 1x1 conv as HMMA GEMM: f1b[s, o] = xt[s,:] @ w_pre1[o,:]^T + b
    hmma_gemm<E_BIASN><<<dim3(3, NTOK / 128), 256>>>(
        xt, 192, wtpre, 192, b_pre1, nullptr, f1b, 192, nullptr, nullptr);

    // 2) depthwise 3x3 (NHWC)
    dwconv_nhwc_kernel<<<NTOK, 192>>>(f1b, w_dw, b_dw, f2);

    // 3) LN + window partition -> p (fp32 + bf16)
    ln_partition_kernel<<<NWIN, 256, TILE_SMEM>>>(f2, ln_g, ln_b, p, pb);

    // 4) qkv = p @ w_qkv + b
    hmma_gemm<E_BIASN><<<dim3(9, NTOK / 128), 256>>>(
        pb, 192, wtq, 192, b_qkv, nullptr, qkvb, 576, nullptr, nullptr);

    // 5) windowed attention -> attn fp32
    attention_kernel<<<NWIN * NHEADS, 64>>>(qkvb, attn);

    // 6) h = gelu(v @ w_g1 + b_g1)
    hmma_gemm<E_GELU><<<dim3(12, NTOK / 128), 256>>>(
        qkvb + 384, 576, wtg1, 192, b_g1, nullptr, hb, 768, nullptr, nullptr);

    // 7) m = (h @ w_g2 + b_g2) * attn
    hmma_gemm<E_MUL><<<dim3(3, NTOK / 128), 256>>>(
        hb, 768, wtg2, 768, b_g2, nullptr, mb, 192, attn, nullptr);

    // 8) fused = m @ w_proj + b_proj  (fp32 + bf16)
    hmma_gemm<E_PROJ><<<dim3(3, NTOK / 128), 256>>>(
        mb, 192, wtp, 192, b_proj, fused, fusedb, 192, nullptr, nullptr);

    // 9) recon GEMM + fused L1 loss
    hmma_gemm<E_LOSS><<<dim3(3, NTOK / 128), 256>>>(
        fusedb, 192, wtr, 192, b_rec, nullptr, nullptr, 192, p, loss);

    // 10) window reverse + residual
    reverse_residual_kernel<<<NWIN, 256, TILE_SMEM>>>(fused, x, out);

    // 11) loss scalar
    if ((size_t)out_size > OUT_MAIN)
        finalize_loss_kernel<<<1, 1>>>(loss, out, (size_t)out_size - 1);
}

// round 4
// speedup vs baseline: 2.4766x; 1.0051x over previous
#include <cuda_runtime.h>
#include <cuda_bf16.h>
#include <math.h>
#include <stdint.h>

// ---------------- problem constants ----------------
#define CDIM   192
#define IMGHW  224
#define HW     (IMGHW*IMGHW)          // 50176
#define BATCH  4
#define HWC    ((size_t)CDIM*HW)
#define NWIN   3136
#define NTOK   200704                 // NWIN * 64 == BATCH*HW
#define NHEADS 6
#define OUT_MAIN ((size_t)BATCH*HWC)  // 38,535,168
#define RECON_DENOM 38535168.0

// ---------------- scratch (device globals) ----------------
__device__ __align__(16) float g_attn[OUT_MAIN/0x1p0 == 0 ? 1 : (size_t)NTOK*192];
__device__ __align__(16) float g_f2  [(size_t)NTOK*192];   // NHWC dwconv out; later fused fp32
__device__ __align__(16) float g_p   [(size_t)NTOK*192];   // fp32 p (for loss)
__device__ __align__(16) __nv_bfloat16 g_pb   [(size_t)NTOK*192];  // xT first, then pb
__device__ __align__(16) __nv_bfloat16 g_qkvb [(size_t)NTOK*576];  // f1b first, then qkv
__device__ __align__(16) __nv_bfloat16 g_hb   [(size_t)NTOK*768];
__device__ __align__(16) __nv_bfloat16 g_mb   [(size_t)NTOK*192];
__device__ __align__(16) __nv_bfloat16 g_fusedb[(size_t)NTOK*192];
__device__ __align__(16) __nv_bfloat16 g_wt_pre [192*192];
__device__ __align__(16) __nv_bfloat16 g_wt_qkv [576*192];
__device__ __align__(16) __nv_bfloat16 g_wt_g1  [768*192];
__device__ __align__(16) __nv_bfloat16 g_wt_g2  [192*768];
__device__ __align__(16) __nv_bfloat16 g_wt_proj[192*192];
__device__ __align__(16) __nv_bfloat16 g_wt_rec [192*192];
__device__ float g_loss[1];

// ---------------- HMMA m16n8k16 bf16 helper ----------------
__device__ __forceinline__ void mma_bf16(float c[4],
    uint32_t a0, uint32_t a1, uint32_t a2, uint32_t a3,
    uint32_t b0, uint32_t b1)
{
    asm volatile(
        "mma.sync.aligned.m16n8k16.row.col.f32.bf16.bf16.f32 "
        "{%0,%1,%2,%3}, {%4,%5,%6,%7}, {%8,%9}, {%0,%1,%2,%3};"
        : "+f"(c[0]), "+f"(c[1]), "+f"(c[2]), "+f"(c[3])
        : "r"(a0), "r"(a1), "r"(a2), "r"(a3), "r"(b0), "r"(b1));
}

// ---------------- HMMA GEMM ----------------
// C[M, Ntot] = A[M,K]bf16 @ BT[Ntot,K]bf16^T + fused epilogue.
// CTA tile 128 x 64, K-chunk 32, double buffered, 256 threads (8 warps 4x2).
enum { E_BIASN = 0, E_GELU = 1, E_MUL = 2, E_PROJ = 3, E_LOSS = 4 };

template<int EPI>
__global__ void __launch_bounds__(256)
hmma_gemm(const __nv_bfloat16* __restrict__ A, int lda,
          const __nv_bfloat16* __restrict__ BT, int K,
          const float* __restrict__ bias,
          float* __restrict__ Cf,
          __nv_bfloat16* __restrict__ Cb, int ldc,
          const float* __restrict__ extra,
          float* __restrict__ lossAcc)
{
    __shared__ __align__(16) __nv_bfloat16 sA[2][128][40];
    __shared__ __align__(16) __nv_bfloat16 sB[2][64][40];
    __shared__ float red[256];

    const int tid = threadIdx.x;
    const int lane = tid & 31, wid = tid >> 5;
    const int wm = wid & 3, wn = wid >> 2;

    const __nv_bfloat16* Ab = A + (size_t)(blockIdx.y * 128) * lda;
    const __nv_bfloat16* Bb = BT + (size_t)(blockIdx.x * 64) * K;

    float acc[2][4][4] = {};
    const int nk = K >> 5;

    // chunk loader: 128x32 A (512 uint4), 64x32 B (256 uint4)
    #define LOAD_CHUNK(buf, k0) do {                                          \
        _Pragma("unroll")                                                     \
        for (int it = 0; it < 2; it++) {                                      \
            int id = tid + it * 256;                                          \
            int r = id >> 2, q = id & 3;                                      \
            *(uint4*)&sA[buf][r][q * 8] =                                     \
                *(const uint4*)(Ab + (size_t)r * lda + (k0) + q * 8);         \
        }                                                                     \
        {                                                                     \
            int r = tid >> 2, q = tid & 3;                                    \
            *(uint4*)&sB[buf][r][q * 8] =                                     \
                *(const uint4*)(Bb + (size_t)r * K + (k0) + q * 8);           \
        }                                                                     \
    } while (0)

    LOAD_CHUNK(0, 0);
    __syncthreads();

    for (int kc = 0; kc < nk; kc++) {
        int b = kc & 1;
        if (kc + 1 < nk) { LOAD_CHUNK(b ^ 1, (kc + 1) * 32); }

        #pragma unroll
        for (int ks = 0; ks < 2; ks++) {
            const int kof = ks * 16 + (lane & 3) * 2;
            uint32_t af[2][4];
            #pragma unroll
            for (int mi = 0; mi < 2; mi++) {
                int r = wm * 32 + mi * 16 + (lane >> 2);
                af[mi][0] = *(const uint32_t*)&sA[b][r][kof];
                af[mi][1] = *(const uint32_t*)&sA[b][r + 8][kof];
                af[mi][2] = *(const uint32_t*)&sA[b][r][kof + 8];
                af[mi][3] = *(const uint32_t*)&sA[b][r + 8][kof + 8];
            }
            uint32_t bfr[4][2];
            #pragma unroll
            for (int ni = 0; ni < 4; ni++) {
                int n = wn * 32 + ni * 8 + (lane >> 2);
                bfr[ni][0] = *(const uint32_t*)&sB[b][n][kof];
                bfr[ni][1] = *(const uint32_t*)&sB[b][n][kof + 8];
            }
            #pragma unroll
            for (int mi = 0; mi < 2; mi++)
                #pragma unroll
                for (int ni = 0; ni < 4; ni++)
                    mma_bf16(acc[mi][ni], af[mi][0], af[mi][1], af[mi][2],
                             af[mi][3], bfr[ni][0], bfr[ni][1]);
        }
        __syncthreads();
    }
    #undef LOAD_CHUNK

    // ---------------- epilogue ----------------
    float lsum = 0.f;
    #pragma unroll
    for (int mi = 0; mi < 2; mi++) {
        #pragma unroll
        for (int ni = 0; ni < 4; ni++) {
            int r0 = blockIdx.y * 128 + wm * 32 + mi * 16 + (lane >> 2);
            int n0 = blockIdx.x * 64 + wn * 32 + ni * 8 + (lane & 3) * 2;
            float b0 = bias[n0], b1 = bias[n0 + 1];
            #pragma unroll
            for (int h = 0; h < 2; h++) {
                int r = r0 + h * 8;
                float v0 = acc[mi][ni][2 * h] + b0;
                float v1 = acc[mi][ni][2 * h + 1] + b1;
                if (EPI == E_GELU) {
                    v0 = 0.5f * v0 * (1.0f + erff(v0 * 0.70710678118654752f));
                    v1 = 0.5f * v1 * (1.0f + erff(v1 * 0.70710678118654752f));
                }
                size_t ci = (size_t)r * ldc + n0;
                if (EPI == E_MUL) { v0 *= extra[ci]; v1 *= extra[ci + 1]; }
                if (EPI == E_LOSS) {
                    lsum += fabsf(v0 - extra[ci]) + fabsf(v1 - extra[ci + 1]);
                } else {
                    __nv_bfloat162 h2 = __floats2bfloat162_rn(v0, v1);
                    *(uint32_t*)(Cb + ci) = *(uint32_t*)&h2;
                    if (EPI == E_PROJ)
                        *(float2*)(Cf + ci) = make_float2(v0, v1);
                }
            }
        }
    }

    if (EPI == E_LOSS) {
        red[tid] = lsum;
        __syncthreads();
        #pragma unroll
        for (int s = 128; s > 0; s >>= 1) {
            if (tid < s) red[tid] += red[tid + s];
            __syncthreads();
        }
        if (tid == 0) atomicAdd(lossAcc, red[0]);
    }
}

// ---------------- x transpose: NCHW fp32 -> NHWC bf16 ----------------
__global__ void __launch_bounds__(256)
transpose_x_kernel(const float* __restrict__ x, __nv_bfloat16* __restrict__ xt)
{
    __shared__ float tile[32][33];
    int s0 = blockIdx.x * 32, c0 = blockIdx.y * 32, b = blockIdx.z;
    int tx = threadIdx.x & 31, ty = threadIdx.x >> 5;   // 32 x 8
    const float* xp = x + (size_t)b * HWC;
    #pragma unroll
    for (int j = 0; j < 4; j++)
        tile[ty + 8 * j][tx] = xp[(size_t)(c0 + ty + 8 * j) * HW + s0 + tx];
    __syncthreads();
    __nv_bfloat16* op = xt + (size_t)b * HW * CDIM;
    #pragma unroll
    for (int j = 0; j < 4; j++)
        op[(size_t)(s0 + ty + 8 * j) * CDIM + c0 + tx] =
            __float2bfloat16(tile[tx][ty + 8 * j]);
}

// ---------------- depthwise 3x3, NHWC, bf16 in / fp32 out ----------------
__global__ void __launch_bounds__(192)
dwconv_nhwc_kernel(const __nv_bfloat16* __restrict__ in,
                   const float* __restrict__ w, const float* __restrict__ bias,
                   float* __restrict__ out)
{
    int c = threadIdx.x;
    int pix = blockIdx.x;
    int b = pix / HW, s = pix % HW;
    int y = s / IMGHW, xq = s % IMGHW;
    const __nv_bfloat16* ip = in + (size_t)b * HW * CDIM;
    float acc = bias[c];
    #pragma unroll
    for (int ky = 0; ky < 3; ky++) {
        int yy = y + ky - 1;
        if (yy < 0 || yy >= IMGHW) continue;
        #pragma unroll
        for (int kx = 0; kx < 3; kx++) {
            int xx = xq + kx - 1;
            if (xx < 0 || xx >= IMGHW) continue;
            acc = fmaf(__bfloat162float(ip[(size_t)(yy * IMGHW + xx) * CDIM + c]),
                       w[c * 9 + ky * 3 + kx], acc);
        }
    }
    out[(size_t)pix * CDIM + c] = acc;
}

// ---------------- LayerNorm + window partition (NHWC fp32 in) ------------
__global__ void __launch_bounds__(256)
ln_partition_kernel(const float* __restrict__ f2,
                    const float* __restrict__ lng, const float* __restrict__ lnb,
                    float* __restrict__ p, __nv_bfloat16* __restrict__ pb)
{
    extern __shared__ float tile[];    // [64][193]
    __shared__ float mu[64], rs[64];
    int win = blockIdx.x;
    int b  = win / 784;
    int wr = win % 784;
    int wy = wr / 28, wx = wr % 28;
    const float* fp = f2 + (size_t)b * HW * CDIM;

    for (int idx = threadIdx.x; idx < 64 * 192; idx += 256) {
        int t = idx / 192, c = idx % 192;
        int iy = t >> 3, ix = t & 7;
        tile[t * 193 + c] =
            fp[(size_t)((wy * 8 + iy) * IMGHW + wx * 8 + ix) * CDIM + c];
    }
    __syncthreads();
    if (threadIdx.x < 64) {
        int t = threadIdx.x;
        float s = 0.f, s2 = 0.f;
        for (int c = 0; c < 192; c++) {
            float v = tile[t * 193 + c];
            s += v; s2 = fmaf(v, v, s2);
        }
        float m = s * (1.0f / 192.0f);
        float var = s2 * (1.0f / 192.0f) - m * m;
        mu[t] = m;
        rs[t] = rsqrtf(var + 1e-6f);
    }
    __syncthreads();
    size_t pbase = (size_t)win * (64 * 192);
    for (int idx = threadIdx.x; idx < 64 * 192; idx += 256) {
        int t = idx / 192, c = idx % 192;
        float v = (tile[t * 193 + c] - mu[t]) * rs[t];
        v = fmaf(v, lng[c], lnb[c]);
        p[pbase + idx] = v;
        pb[pbase + idx] = __float2bfloat16(v);
    }
}

// ---------------- windowed multi-head attention (bf16 qkv in) ------------
__global__ void __launch_bounds__(64)
attention_kernel(const __nv_bfloat16* __restrict__ qkv, float* __restrict__ outat)
{
    __shared__ float ks[64][33];
    __shared__ float vs[64][33];
    __shared__ float ps[64][65];
    int bid = blockIdx.x;
    int win = bid / NHEADS, h = bid % NHEADS;
    size_t qbase = (size_t)win * 64 * 576;
    int hc = h * 32;

    for (int idx = threadIdx.x; idx < 64 * 32; idx += 64) {
        int t = idx >> 5, c = idx & 31;
        ks[t][c] = __bfloat162float(qkv[qbase + (size_t)t * 576 + 192 + hc + c]);
        vs[t][c] = __bfloat162float(qkv[qbase + (size_t)t * 576 + 384 + hc + c]);
    }
    __syncthreads();

    int r = threadIdx.x;
    float q[32];
    const __nv_bfloat16* qp = &qkv[qbase + (size_t)r * 576 + hc];
    #pragma unroll
    for (int c = 0; c < 32; c++) q[c] = __bfloat162float(qp[c]);

    float mx = -1e30f;
    for (int t = 0; t < 64; t++) {
        float d = 0.f;
        #pragma unroll
        for (int c = 0; c < 32; c++) d = fmaf(q[c], ks[t][c], d);
        d *= 0.17677669529663687f;
        ps[r][t] = d;
        mx = fmaxf(mx, d);
    }
    float sum = 0.f;
    for (int t = 0; t < 64; t++) {
        float e = expf(ps[r][t] - mx);
        ps[r][t] = e;
        sum += e;
    }
    float inv = 1.0f / sum;
    float* op = &outat[((size_t)win * 64 + r) * 192 + hc];
    for (int c = 0; c < 32; c++) {
        float a = 0.f;
        for (int t = 0; t < 64; t++) a = fmaf(ps[r][t], vs[t][c], a);
        op[c] = a * inv;
    }
}

// ---------------- window reverse + residual (to NCHW) ----------------
__global__ void __launch_bounds__(256)
reverse_residual_kernel(const float* __restrict__ fused,
                        const float* __restrict__ xin,
                        float* __restrict__ out)
{
    extern __shared__ float tile[];    // [64][193]
    int win = blockIdx.x;
    size_t fb = (size_t)win * (64 * 192);
    for (int idx = threadIdx.x; idx < 64 * 192; idx += 256) {
        int t = idx / 192, c = idx % 192;
        tile[t * 193 + c] = fused[fb + idx];
    }
    __syncthreads();
    int b  = win / 784;
    int wr = win % 784;
    int wy = wr / 28, wx = wr % 28;
    size_t base = (size_t)b * HWC + (size_t)(wy * 8) * IMGHW + wx * 8;
    for (int idx = threadIdx.x; idx < 64 * 192; idx += 256) {
        int c = idx >> 6, t = idx & 63;
        int iy = t >> 3, ix = t & 7;
        size_t o = base + (size_t)c * HW + iy * IMGHW + ix;
        out[o] = tile[t * 193 + c] + xin[o];
    }
}

// ---------------- weight prep ----------------
__global__ void transpose_w_kernel(const float* __restrict__ w,
                                   __nv_bfloat16* __restrict__ wt, int K, int N)
{
    int i = blockIdx.x * 256 + threadIdx.x;
    if (i < K * N) {
        int k = i / N, n = i % N;
        wt[n * K + k] = __float2bfloat16(w[i]);
    }
}
__global__ void convert_w_kernel(const float* __restrict__ w,
                                 __nv_bfloat16* __restrict__ wt, int n)
{
    int i = blockIdx.x * 256 + threadIdx.x;
    if (i < n) wt[i] = __float2bfloat16(w[i]);
}

// ---------------- tiny helpers ----------------
__global__ void zero_loss_kernel(float* l) { *l = 0.f; }
__global__ void finalize_loss_kernel(const float* l, float* out, size_t pos)
{
    out[pos] = l[0] * (float)(0.1 / RECON_DENOM);
}

// ---------------- launch ----------------
extern "C" void kernel_launch(void* const* d_in, const int* in_sizes, int n_in,
                              void* d_out, int out_size)
{
    const float* x      = (const float*)d_in[0];
    const float* w_pre1 = (const float*)d_in[1];
    const float* b_pre1 = (const float*)d_in[2];
    const float* w_dw   = (const float*)d_in[3];
    const float* b_dw   = (const float*)d_in[4];
    const float* ln_g   = (const float*)d_in[5];
    const float* ln_b   = (const float*)d_in[6];
    const float* w_qkv  = (const float*)d_in[7];
    const float* b_qkv  = (const float*)d_in[8];
    const float* w_proj = (const float*)d_in[9];
    const float* b_proj = (const float*)d_in[10];
    const float* w_g1   = (const float*)d_in[11];
    const float* b_g1   = (const float*)d_in[12];
    const float* w_g2   = (const float*)d_in[13];
    const float* b_g2   = (const float*)d_in[14];
    const float* w_rec  = (const float*)d_in[15];
    const float* b_rec  = (const float*)d_in[16];
    float* out = (float*)d_out;

    float *attn, *f2, *p, *loss;
    __nv_bfloat16 *pb, *qkvb, *hb, *mb, *fusedb;
    __nv_bfloat16 *wtpre, *wtq, *wtg1, *wtg2, *wtp, *wtr;
    cudaGetSymbolAddress((void**)&attn,  g_attn);
    cudaGetSymbolAddress((void**)&f2,    g_f2);
    cudaGetSymbolAddress((void**)&p,     g_p);
    cudaGetSymbolAddress((void**)&pb,    g_pb);
    cudaGetSymbolAddress((void**)&qkvb,  g_qkvb);
    cudaGetSymbolAddress((void**)&hb,    g_hb);
    cudaGetSymbolAddress((void**)&mb,    g_mb);
    cudaGetSymbolAddress((void**)&fusedb, g_fusedb);
    cudaGetSymbolAddress((void**)&wtpre, g_wt_pre);
    cudaGetSymbolAddress((void**)&wtq,   g_wt_qkv);
    cudaGetSymbolAddress((void**)&wtg1,  g_wt_g1);
    cudaGetSymbolAddress((void**)&wtg2,  g_wt_g2);
    cudaGetSymbolAddress((void**)&wtp,   g_wt_proj);
    cudaGetSymbolAddress((void**)&wtr,   g_wt_rec);
    cudaGetSymbolAddress((void**)&loss,  g_loss);

    __nv_bfloat16* xt  = pb;     // xT dead before pb is written (by LN)
    __nv_bfloat16* f1b = qkvb;   // f1b dead before qkv GEMM writes
    float* fused = f2;           // f2 dead after LN

    const int TILE_SMEM = 64 * 193 * 4;
    cudaFuncSetAttribute(ln_partition_kernel,
                         cudaFuncAttributeMaxDynamicSharedMemorySize, TILE_SMEM);
    cudaFuncSetAttribute(reverse_residual_kernel,
                         cudaFuncAttributeMaxDynamicSharedMemorySize, TILE_SMEM);

    zero_loss_kernel<<<1, 1>>>(loss);

    // weight prep (tiny)
    convert_w_kernel<<<(192*192 + 255) / 256, 256>>>(w_pre1, wtpre, 192*192);
    transpose_w_kernel<<<(192*576 + 255) / 256, 256>>>(w_qkv, wtq, 192, 576);
    transpose_w_kernel<<<(192*768 + 255) / 256, 256>>>(w_g1, wtg1, 192, 768);
    transpose_w_kernel<<<(768*192 + 255) / 256, 256>>>(w_g2, wtg2, 768, 192);
    transpose_w_kernel<<<(192*192 + 255) / 256, 256>>>(w_proj, wtp, 192, 192);
    transpose_w_kernel<<<(192*192 + 255) / 256, 256>>>(w_rec, wtr, 192, 192);

    // 0) x -> NHWC bf16
    transpose_x_kernel<<<dim3(HW / 32, CDIM / 32, BATCH), 256>>>(x, xt);

    // 1) 1x1 conv as HMMA GEMM: f1b[s, o] = xt[s,:] @ w_pre1[o,:]^T + b
    hmma_gemm<E_BIASN><<<dim3(3, NTOK / 128), 256>>>(
        xt, 192, wtpre, 192, b_pre1, nullptr, f1b, 192, nullptr, nullptr);

    // 2) depthwise 3x3 (NHWC)
    dwconv_nhwc_kernel<<<NTOK, 192>>>(f1b, w_dw, b_dw, f2);

    // 3) LN + window partition -> p (fp32 + bf16)
    ln_partition_kernel<<<NWIN, 256, TILE_SMEM>>>(f2, ln_g, ln_b, p, pb);

    // 4) qkv = p @ w_qkv + b
    hmma_gemm<E_BIASN><<<dim3(9, NTOK / 128), 256>>>(
        pb, 192, wtq, 192, b_qkv, nullptr, qkvb, 576, nullptr, nullptr);

    // 5) windowed attention -> attn fp32
    attention_kernel<<<NWIN * NHEADS, 64>>>(qkvb, attn);

    // 6) h = gelu(v @ w_g1 + b_g1)
    hmma_gemm<E_GELU><<<dim3(12, NTOK / 128), 256>>>(
        qkvb + 384, 576, wtg1, 192, b_g1, nullptr, hb, 768, nullptr, nullptr);

    // 7) m = (h @ w_g2 + b_g2) * attn
    hmma_gemm<E_MUL><<<dim3(3, NTOK / 128), 256>>>(
        hb, 768, wtg2, 768, b_g2, nullptr, mb, 192, attn, nullptr);

    // 8) fused = m @ w_proj + b_proj  (fp32 + bf16)
    hmma_gemm<E_PROJ><<<dim3(3, NTOK / 128), 256>>>(
        mb, 192, wtp, 192, b_proj, fused, fusedb, 192, nullptr, nullptr);

    // 9) recon GEMM + fused L1 loss
    hmma_gemm<E_LOSS><<<dim3(3, NTOK / 128), 256>>>(
        fusedb, 192, wtr, 192, b_rec, nullptr, nullptr, 192, p, loss);

    // 10) window reverse + residual
    reverse_residual_kernel<<<NWIN, 256, TILE_SMEM>>>(fused, x, out);

    // 11) loss scalar
    if ((size_t)out_size > OUT_MAIN)
        finalize_loss_kernel<<<1, 1>>>(loss, out, (size_t)out_size - 1);
}